// round 1
// baseline (speedup 1.0000x reference)
#include <cuda_runtime.h>
#include <math.h>

// SmoothTopKGate: s (nrows, 8) fp32 -> sigmoid((s - theta)/tau), theta via
// Newton with GLOBAL stopping rule mean(f) < TOL (cumulative), matching the
// JAX reference's fixed-point semantics exactly:
//   n* = first iteration i where mean_rows(f(theta_i)) < TOL  (theta_i = i plain
//   Newton updates from theta0 = 3rd largest). All rows apply exactly n* updates.

constexpr int    S_DIM     = 8;
constexpr float  KSEL      = 2.0f;
constexpr float  INV_TAU   = 100.0f;      // fp32(1.0/0.01) == 100.0f (matches jax const)
constexpr int    MAX_ITER  = 100;
constexpr double TOL       = 1e-3;
constexpr float  FP_SCALE  = 1073741824.0f;   // 2^30 fixed point for deterministic sums
constexpr double FP_SCALE_D = 1073741824.0;
constexpr float  EXIT_EPS  = 1e-6f;       // per-row early exit in pass 1 (mean bias <= 1e-6)

__device__ long long g_sums[MAX_ITER];
__device__ int       g_nstar;

__device__ __forceinline__ float sigmoid_f(float x) {
    // 1/(1+e^-x): EX2 + RCP (2 MUFU). Handles overflow: exp->inf -> rcp -> 0,
    // matching fp32 reference behavior at the tails.
    return __fdividef(1.0f, 1.0f + __expf(-x));
}

__device__ __forceinline__ void eval_fg(const float t[S_DIM], float theta,
                                        float& f, float& g) {
    float fs = 0.0f, gs = 0.0f;
#pragma unroll
    for (int j = 0; j < S_DIM; ++j) {
        float x = (t[j] - theta) * INV_TAU;
        float m = sigmoid_f(x);
        fs += m;
        gs += m * (1.0f - m);
    }
    f = fs - KSEL;
    g = gs;
}

__device__ __forceinline__ float third_largest(const float t[S_DIM]) {
    // running top-3 (a1 >= a2 >= a3) via min/max insertion network
    float a1 = fmaxf(t[0], t[1]);
    float a2 = fminf(t[0], t[1]);
    float a3 = __int_as_float(0xff800000);  // -inf
#pragma unroll
    for (int j = 2; j < S_DIM; ++j) {
        float v  = t[j];
        float m1 = fmaxf(a1, v);
        float r1 = fminf(a1, v);
        float m2 = fmaxf(a2, r1);
        float r2 = fminf(a2, r1);
        float m3 = fmaxf(a3, r2);
        a1 = m1; a2 = m2; a3 = m3;
    }
    return a3;   // (k+1)-th largest for k=2
}

__device__ __forceinline__ void load_row(const float* __restrict__ s, int row,
                                         float t[S_DIM]) {
    const float4* p = reinterpret_cast<const float4*>(s + (size_t)row * S_DIM);
    float4 v0 = p[0];
    float4 v1 = p[1];
    t[0] = v0.x; t[1] = v0.y; t[2] = v0.z; t[3] = v0.w;
    t[4] = v1.x; t[5] = v1.y; t[6] = v1.z; t[7] = v1.w;
}

__global__ void k_zero() {
    for (int i = threadIdx.x; i < MAX_ITER; i += blockDim.x) g_sums[i] = 0;
    if (threadIdx.x == 0) g_nstar = MAX_ITER;
}

__global__ void k_pass1(const float* __restrict__ s, int nrows) {
    __shared__ unsigned long long ss[MAX_ITER];
    for (int i = threadIdx.x; i < MAX_ITER; i += blockDim.x) ss[i] = 0ULL;
    __syncthreads();

    int row = blockIdx.x * blockDim.x + threadIdx.x;
    if (row < nrows) {
        float t[S_DIM];
        load_row(s, row, t);
        float theta = third_largest(t);
#pragma unroll 1
        for (int i = 0; i < MAX_ITER; ++i) {
            float f, g;
            eval_fg(t, theta, f, g);
            long long fx = llrintf(f * FP_SCALE);
            atomicAdd(&ss[i], (unsigned long long)fx);
            if (fabsf(f) < EXIT_EPS) break;      // converged: future |f| <= eps, treat 0
            if (!(g > 0.0f)) break;              // safety (unreachable for real data)
            float df = -100.0f * g;              // matches -(1/tau)*g in fp32
            theta = theta - __fdividef(f, df);
        }
    }

    __syncthreads();
    for (int i = threadIdx.x; i < MAX_ITER; i += blockDim.x)
        if (ss[i])
            atomicAdd(reinterpret_cast<unsigned long long*>(&g_sums[i]), ss[i]);
}

__global__ void k_pick(int nrows) {
    if (threadIdx.x == 0 && blockIdx.x == 0) {
        double denom = (double)nrows * FP_SCALE_D;
        int n = MAX_ITER;
        for (int i = 0; i < MAX_ITER; ++i) {
            double mean = (double)g_sums[i] / denom;
            if (mean < TOL) { n = i; break; }
        }
        g_nstar = n;
    }
}

__global__ void k_pass2(const float* __restrict__ s, float* __restrict__ out,
                        int nrows) {
    int row = blockIdx.x * blockDim.x + threadIdx.x;
    if (row >= nrows) return;

    float t[S_DIM];
    load_row(s, row, t);
    float theta = third_largest(t);

    int n = g_nstar;   // uniform across grid -> no divergence
#pragma unroll 1
    for (int i = 0; i < n; ++i) {
        float f, g;
        eval_fg(t, theta, f, g);
        if (!(g > 0.0f)) break;                  // safety (unreachable)
        float df = -100.0f * g;
        theta = theta - __fdividef(f, df);
    }

    float4 o0, o1;
    o0.x = sigmoid_f((t[0] - theta) * INV_TAU);
    o0.y = sigmoid_f((t[1] - theta) * INV_TAU);
    o0.z = sigmoid_f((t[2] - theta) * INV_TAU);
    o0.w = sigmoid_f((t[3] - theta) * INV_TAU);
    o1.x = sigmoid_f((t[4] - theta) * INV_TAU);
    o1.y = sigmoid_f((t[5] - theta) * INV_TAU);
    o1.z = sigmoid_f((t[6] - theta) * INV_TAU);
    o1.w = sigmoid_f((t[7] - theta) * INV_TAU);

    float4* po = reinterpret_cast<float4*>(out + (size_t)row * S_DIM);
    po[0] = o0;
    po[1] = o1;
}

extern "C" void kernel_launch(void* const* d_in, const int* in_sizes, int n_in,
                              void* d_out, int out_size) {
    const float* s = (const float*)d_in[0];
    float* out = (float*)d_out;
    int nrows = in_sizes[0] / S_DIM;

    k_zero<<<1, 128>>>();

    const int threads = 256;
    int blocks = (nrows + threads - 1) / threads;
    k_pass1<<<blocks, threads>>>(s, nrows);
    k_pick<<<1, 32>>>(nrows);
    k_pass2<<<blocks, threads>>>(s, out, nrows);
}

// round 2
// speedup vs baseline: 1.2763x; 1.2763x over previous
#include <cuda_runtime.h>
#include <math.h>

// SmoothTopKGate: s (nrows, 8) fp32 -> sigmoid((s - theta)/tau).
// theta: Newton from theta0 = 3rd largest, with GLOBAL stop rule
//   n* = first i with mean_rows(f(theta_i)) < TOL; all rows apply n* updates.
//
// Pass 1 computes per-iteration f-sums. Exact fixed-point optimization:
// once theta_new == theta (bitwise), the row state is frozen forever and all
// future f_i equal the current f EXACTLY -> stop iterating and record the
// constant tail contribution in g_tail[L] (suffix-carry in k_pick).

constexpr int    S_DIM     = 8;
constexpr float  KSEL      = 2.0f;
constexpr float  INV_TAU   = 100.0f;
constexpr int    MAX_ITER  = 100;
constexpr double TOL       = 1e-3;
constexpr float  FP_SCALE  = 4194304.0f;      // 2^22: |f|<=6 -> |fx|<=2.5e7; warp sum <= 8e8 < 2^31
constexpr double FP_SCALE_D = 4194304.0;
constexpr int    NW        = 8;               // warps per 256-thread block

__device__ long long g_sums[MAX_ITER];   // explicit per-iteration sums (fixed point)
__device__ long long g_tail[MAX_ITER];   // constant-tail contributions starting at iter i
__device__ int       g_nstar;

__device__ __forceinline__ float sigmoid_f(float x) {
    return __fdividef(1.0f, 1.0f + __expf(-x));
}

__device__ __forceinline__ void eval_fg(const float t[S_DIM], float theta,
                                        float& f, float& g) {
    float fs = 0.0f, gs = 0.0f;
#pragma unroll
    for (int j = 0; j < S_DIM; ++j) {
        float x = (t[j] - theta) * INV_TAU;
        float m = sigmoid_f(x);
        fs += m;
        gs += m * (1.0f - m);
    }
    f = fs - KSEL;
    g = gs;
}

__device__ __forceinline__ float third_largest(const float t[S_DIM]) {
    float a1 = fmaxf(t[0], t[1]);
    float a2 = fminf(t[0], t[1]);
    float a3 = __int_as_float(0xff800000);  // -inf
#pragma unroll
    for (int j = 2; j < S_DIM; ++j) {
        float v  = t[j];
        float m1 = fmaxf(a1, v);
        float r1 = fminf(a1, v);
        float m2 = fmaxf(a2, r1);
        float r2 = fminf(a2, r1);
        float m3 = fmaxf(a3, r2);
        a1 = m1; a2 = m2; a3 = m3;
    }
    return a3;   // (k+1)-th largest for k=2
}

__device__ __forceinline__ void load_row(const float* __restrict__ s, int row,
                                         float t[S_DIM]) {
    const float4* p = reinterpret_cast<const float4*>(s + (size_t)row * S_DIM);
    float4 v0 = p[0];
    float4 v1 = p[1];
    t[0] = v0.x; t[1] = v0.y; t[2] = v0.z; t[3] = v0.w;
    t[4] = v1.x; t[5] = v1.y; t[6] = v1.z; t[7] = v1.w;
}

__global__ void k_zero() {
    for (int i = threadIdx.x; i < MAX_ITER; i += blockDim.x) {
        g_sums[i] = 0;
        g_tail[i] = 0;
    }
    if (threadIdx.x == 0) g_nstar = MAX_ITER;
}

__global__ void __launch_bounds__(256) k_pass1(const float* __restrict__ s, int nrows) {
    __shared__ long long ss[NW][MAX_ITER];
    const int tid  = threadIdx.x;
    const int wid  = tid >> 5;
    const int lane = tid & 31;

    for (int i = tid; i < NW * MAX_ITER; i += blockDim.x)
        (&ss[0][0])[i] = 0;
    __syncthreads();

    int row = blockIdx.x * blockDim.x + tid;
    bool valid = row < nrows;

    float t[S_DIM];
    float theta = 0.0f;
    if (valid) {
        load_row(s, row, t);
        theta = third_largest(t);
    } else {
#pragma unroll
        for (int j = 0; j < S_DIM; ++j) t[j] = 0.0f;
    }

    bool frozen = !valid;       // frozen lanes contribute a constant (0 for invalid)
    int  i = 0;
    int  wsum = 0;

#pragma unroll 1
    for (; i < MAX_ITER; ++i) {
        float f, g;
        eval_fg(t, theta, f, g);            // frozen lanes recompute identical f
        int fx = valid ? __float2int_rn(f * FP_SCALE) : 0;
        wsum = __reduce_add_sync(0xffffffffu, fx);
        if (lane == 0) ss[wid][i] = (long long)wsum;

        if (!frozen) {
            float thn = theta - __fdividef(f, -100.0f * g);
            if ((g > 0.0f) && (thn != theta)) theta = thn;
            else frozen = true;             // exact fp32 fixed point (or safety)
        }
        if (__all_sync(0xffffffffu, frozen)) { ++i; break; }
    }

    // Constant tail: for all iterations >= i this warp would contribute wsum.
    if (lane == 0 && i < MAX_ITER && wsum != 0)
        atomicAdd(reinterpret_cast<unsigned long long*>(&g_tail[i]),
                  (unsigned long long)(long long)wsum);

    __syncthreads();
    for (int idx = tid; idx < MAX_ITER; idx += blockDim.x) {
        long long tot = 0;
#pragma unroll
        for (int w = 0; w < NW; ++w) tot += ss[w][idx];
        if (tot)
            atomicAdd(reinterpret_cast<unsigned long long*>(&g_sums[idx]),
                      (unsigned long long)tot);
    }
}

__global__ void k_pick(int nrows) {
    if (threadIdx.x == 0 && blockIdx.x == 0) {
        double denom = (double)nrows * FP_SCALE_D;
        long long carry = 0;
        int n = MAX_ITER;
        for (int i = 0; i < MAX_ITER; ++i) {
            carry += g_tail[i];
            double mean = (double)(g_sums[i] + carry) / denom;
            if (mean < TOL) { n = i; break; }
        }
        g_nstar = n;
    }
}

__global__ void __launch_bounds__(256) k_pass2(const float* __restrict__ s,
                                               float* __restrict__ out, int nrows) {
    int row = blockIdx.x * blockDim.x + threadIdx.x;
    if (row >= nrows) return;

    float t[S_DIM];
    load_row(s, row, t);
    float theta = third_largest(t);

    int n = g_nstar;   // uniform across grid
#pragma unroll 1
    for (int i = 0; i < n; ++i) {
        float f, g;
        eval_fg(t, theta, f, g);
        float thn = theta - __fdividef(f, -100.0f * g);
        if ((g > 0.0f) && (thn != theta)) theta = thn;
        else break;                         // frozen: remaining updates are no-ops
    }

    float4 o0, o1;
    o0.x = sigmoid_f((t[0] - theta) * INV_TAU);
    o0.y = sigmoid_f((t[1] - theta) * INV_TAU);
    o0.z = sigmoid_f((t[2] - theta) * INV_TAU);
    o0.w = sigmoid_f((t[3] - theta) * INV_TAU);
    o1.x = sigmoid_f((t[4] - theta) * INV_TAU);
    o1.y = sigmoid_f((t[5] - theta) * INV_TAU);
    o1.z = sigmoid_f((t[6] - theta) * INV_TAU);
    o1.w = sigmoid_f((t[7] - theta) * INV_TAU);

    float4* po = reinterpret_cast<float4*>(out + (size_t)row * S_DIM);
    po[0] = o0;
    po[1] = o1;
}

extern "C" void kernel_launch(void* const* d_in, const int* in_sizes, int n_in,
                              void* d_out, int out_size) {
    const float* s = (const float*)d_in[0];
    float* out = (float*)d_out;
    int nrows = in_sizes[0] / S_DIM;

    k_zero<<<1, 128>>>();

    const int threads = 256;
    int blocks = (nrows + threads - 1) / threads;
    k_pass1<<<blocks, threads>>>(s, nrows);
    k_pick<<<1, 32>>>(nrows);
    k_pass2<<<blocks, threads>>>(s, out, nrows);
}

// round 3
// speedup vs baseline: 5.3655x; 4.2039x over previous
#include <cuda_runtime.h>
#include <math.h>

// SmoothTopKGate: s (nrows, 8) fp32 -> sigmoid((s - theta)/tau).
// n* = first i with mean_rows(f(theta_i)) < TOL (global stop), then all rows
// apply exactly n* Newton updates from theta0 = 3rd largest.
//
// Fast path: pass1 capped at C=12 iterations (n* is ~6-7 by Newton decay rate;
// sums for i<C are exact). If no crossing found below C, an exact full-depth
// fallback recomputes the sums (early-exits when unused).

constexpr int    S_DIM      = 8;
constexpr float  KSEL       = 2.0f;
constexpr float  INV_TAU    = 100.0f;
constexpr int    MAX_ITER   = 100;
constexpr int    CAP        = 12;             // fast-path iteration cap (n* ~ 6-7)
constexpr double TOL        = 1e-3;
constexpr float  FP_SCALE   = 4194304.0f;     // 2^22 fixed point (warp sum < 2^31)
constexpr double FP_SCALE_D = 4194304.0;
constexpr int    NW         = 8;              // warps per 256-thread block

__device__ long long g_sums[CAP];
__device__ long long g_tail[CAP];
__device__ long long g_sums_fb[MAX_ITER];
__device__ long long g_tail_fb[MAX_ITER];
__device__ int       g_nstar;

__device__ __forceinline__ float sigmoid_f(float x) {
    return __fdividef(1.0f, 1.0f + __expf(-x));
}

__device__ __forceinline__ void eval_fg(const float t[S_DIM], float theta,
                                        float& f, float& g) {
    float fs = 0.0f, gs = 0.0f;
#pragma unroll
    for (int j = 0; j < S_DIM; ++j) {
        float x = (t[j] - theta) * INV_TAU;
        float m = sigmoid_f(x);
        fs += m;
        gs += m * (1.0f - m);
    }
    f = fs - KSEL;
    g = gs;
}

__device__ __forceinline__ float third_largest(const float t[S_DIM]) {
    float a1 = fmaxf(t[0], t[1]);
    float a2 = fminf(t[0], t[1]);
    float a3 = __int_as_float(0xff800000);  // -inf
#pragma unroll
    for (int j = 2; j < S_DIM; ++j) {
        float v  = t[j];
        float m1 = fmaxf(a1, v);
        float r1 = fminf(a1, v);
        float m2 = fmaxf(a2, r1);
        float r2 = fminf(a2, r1);
        float m3 = fmaxf(a3, r2);
        a1 = m1; a2 = m2; a3 = m3;
    }
    return a3;   // (k+1)-th largest for k=2
}

__device__ __forceinline__ void load_row(const float* __restrict__ s, int row,
                                         float t[S_DIM]) {
    const float4* p = reinterpret_cast<const float4*>(s + (size_t)row * S_DIM);
    float4 v0 = p[0];
    float4 v1 = p[1];
    t[0] = v0.x; t[1] = v0.y; t[2] = v0.z; t[3] = v0.w;
    t[4] = v1.x; t[5] = v1.y; t[6] = v1.z; t[7] = v1.w;
}

__global__ void k_zero() {
    for (int i = threadIdx.x; i < MAX_ITER; i += blockDim.x) {
        g_sums_fb[i] = 0;
        g_tail_fb[i] = 0;
        if (i < CAP) { g_sums[i] = 0; g_tail[i] = 0; }
    }
    if (threadIdx.x == 0) g_nstar = -2;
}

// ---------------- fast path: capped pass 1 ----------------
__global__ void __launch_bounds__(256) k_pass1(const float* __restrict__ s, int nrows) {
    __shared__ long long ss[NW][CAP];
    const int tid  = threadIdx.x;
    const int wid  = tid >> 5;
    const int lane = tid & 31;

    for (int i = tid; i < NW * CAP; i += blockDim.x)
        (&ss[0][0])[i] = 0;
    __syncthreads();

    int row = blockIdx.x * blockDim.x + tid;
    bool valid = row < nrows;

    float t[S_DIM];
    float theta = 0.0f;
    if (valid) {
        load_row(s, row, t);
        theta = third_largest(t);
    } else {
#pragma unroll
        for (int j = 0; j < S_DIM; ++j) t[j] = 0.0f;
    }

    bool frozen = !valid;
    int  i = 0;
    int  wsum = 0;

#pragma unroll 1
    for (; i < CAP; ++i) {
        float f, g;
        eval_fg(t, theta, f, g);
        int fx = valid ? __float2int_rn(f * FP_SCALE) : 0;
        wsum = __reduce_add_sync(0xffffffffu, fx);
        if (lane == 0) ss[wid][i] = (long long)wsum;

        if (!frozen) {
            float thn = theta - __fdividef(f, -100.0f * g);
            if ((g > 0.0f) && (thn != theta)) theta = thn;
            else frozen = true;
        }
        if (__all_sync(0xffffffffu, frozen)) { ++i; break; }
    }

    if (lane == 0 && i < CAP && wsum != 0)
        atomicAdd(reinterpret_cast<unsigned long long*>(&g_tail[i]),
                  (unsigned long long)(long long)wsum);

    __syncthreads();
    for (int idx = tid; idx < CAP; idx += blockDim.x) {
        long long tot = 0;
#pragma unroll
        for (int w = 0; w < NW; ++w) tot += ss[w][idx];
        if (tot)
            atomicAdd(reinterpret_cast<unsigned long long*>(&g_sums[idx]),
                      (unsigned long long)tot);
    }
}

__global__ void k_pick(int nrows) {
    if (threadIdx.x == 0 && blockIdx.x == 0) {
        double denom = (double)nrows * FP_SCALE_D;
        long long carry = 0;
        int n = -1;   // -1 => fallback required
        for (int i = 0; i < CAP; ++i) {
            carry += g_tail[i];
            double mean = (double)(g_sums[i] + carry) / denom;
            if (mean < TOL) { n = i; break; }
        }
        g_nstar = n;
    }
}

// ---------------- exact fallback (early-exits when fast path succeeded) ----------------
__global__ void __launch_bounds__(256) k_fb_pass1(const float* __restrict__ s, int nrows) {
    if (g_nstar >= 0) return;   // uniform: fast path found n*

    __shared__ long long ss[NW][MAX_ITER];
    const int tid  = threadIdx.x;
    const int wid  = tid >> 5;
    const int lane = tid & 31;

    for (int i = tid; i < NW * MAX_ITER; i += blockDim.x)
        (&ss[0][0])[i] = 0;
    __syncthreads();

    const int stride = gridDim.x * blockDim.x;
    for (int row = blockIdx.x * blockDim.x + tid; ; row += stride) {
        bool valid = row < nrows;
        if (!__any_sync(0xffffffffu, valid)) break;

        float t[S_DIM];
        float theta = 0.0f;
        if (valid) {
            load_row(s, row, t);
            theta = third_largest(t);
        } else {
#pragma unroll
            for (int j = 0; j < S_DIM; ++j) t[j] = 0.0f;
        }

        bool frozen = !valid;
        int  i = 0;
        int  wsum = 0;

#pragma unroll 1
        for (; i < MAX_ITER; ++i) {
            float f, g;
            eval_fg(t, theta, f, g);
            int fx = valid ? __float2int_rn(f * FP_SCALE) : 0;
            wsum = __reduce_add_sync(0xffffffffu, fx);
            if (lane == 0) ss[wid][i] += (long long)wsum;

            if (!frozen) {
                float thn = theta - __fdividef(f, -100.0f * g);
                if ((g > 0.0f) && (thn != theta)) theta = thn;
                else frozen = true;
            }
            if (__all_sync(0xffffffffu, frozen)) { ++i; break; }
        }

        if (lane == 0 && i < MAX_ITER && wsum != 0) {
            // constant tail from iter i onwards for this warp's current rows
            atomicAdd(reinterpret_cast<unsigned long long*>(&g_tail_fb[i]),
                      (unsigned long long)(long long)wsum);
        }
    }

    __syncthreads();
    for (int idx = tid; idx < MAX_ITER; idx += blockDim.x) {
        long long tot = 0;
#pragma unroll
        for (int w = 0; w < NW; ++w) tot += ss[w][idx];
        if (tot)
            atomicAdd(reinterpret_cast<unsigned long long*>(&g_sums_fb[idx]),
                      (unsigned long long)tot);
    }
}

__global__ void k_fb_pick(int nrows) {
    if (threadIdx.x == 0 && blockIdx.x == 0) {
        if (g_nstar >= 0) return;
        double denom = (double)nrows * FP_SCALE_D;
        long long carry = 0;
        int n = MAX_ITER;
        for (int i = 0; i < MAX_ITER; ++i) {
            carry += g_tail_fb[i];
            double mean = (double)(g_sums_fb[i] + carry) / denom;
            if (mean < TOL) { n = i; break; }
        }
        g_nstar = n;
    }
}

// ---------------- pass 2 ----------------
__global__ void __launch_bounds__(256) k_pass2(const float* __restrict__ s,
                                               float* __restrict__ out, int nrows) {
    int row = blockIdx.x * blockDim.x + threadIdx.x;
    if (row >= nrows) return;

    float t[S_DIM];
    load_row(s, row, t);
    float theta = third_largest(t);

    int n = g_nstar;   // uniform across grid
#pragma unroll 1
    for (int i = 0; i < n; ++i) {
        float f, g;
        eval_fg(t, theta, f, g);
        float thn = theta - __fdividef(f, -100.0f * g);
        if ((g > 0.0f) && (thn != theta)) theta = thn;
        else break;                         // frozen: remaining updates are no-ops
    }

    float4 o0, o1;
    o0.x = sigmoid_f((t[0] - theta) * INV_TAU);
    o0.y = sigmoid_f((t[1] - theta) * INV_TAU);
    o0.z = sigmoid_f((t[2] - theta) * INV_TAU);
    o0.w = sigmoid_f((t[3] - theta) * INV_TAU);
    o1.x = sigmoid_f((t[4] - theta) * INV_TAU);
    o1.y = sigmoid_f((t[5] - theta) * INV_TAU);
    o1.z = sigmoid_f((t[6] - theta) * INV_TAU);
    o1.w = sigmoid_f((t[7] - theta) * INV_TAU);

    float4* po = reinterpret_cast<float4*>(out + (size_t)row * S_DIM);
    po[0] = o0;
    po[1] = o1;
}

extern "C" void kernel_launch(void* const* d_in, const int* in_sizes, int n_in,
                              void* d_out, int out_size) {
    const float* s = (const float*)d_in[0];
    float* out = (float*)d_out;
    int nrows = in_sizes[0] / S_DIM;

    k_zero<<<1, 128>>>();

    const int threads = 256;
    int blocks = (nrows + threads - 1) / threads;
    k_pass1<<<blocks, threads>>>(s, nrows);
    k_pick<<<1, 32>>>(nrows);
    k_fb_pass1<<<2960, threads>>>(s, nrows);   // early-exits when fast path succeeded
    k_fb_pick<<<1, 32>>>(nrows);
    k_pass2<<<blocks, threads>>>(s, out, nrows);
}

// round 4
// speedup vs baseline: 7.6028x; 1.4170x over previous
#include <cuda_runtime.h>
#include <math.h>

// SmoothTopKGate: s (nrows, 8) fp32 -> sigmoid((s - theta)/tau).
// n* = first i with mean_rows(f(theta_i)) < TOL (global stop), then all rows
// apply exactly n* Newton updates from theta0 = 3rd largest.
//
// Fast path: pass1 runs exactly CAP=10 iterations per row, accumulates exact
// per-iteration f-sums (2^22 fixed point, order-independent -> deterministic),
// and stores the theta trajectory to global planes. Last block picks n*.
// Pass2 reads theta_{n*} directly and emits the 8 gates (DRAM-bound).
// If no crossing below CAP, an exact full-depth fallback recomputes everything
// (early-exits in ~5us when unused); pass2 then replays Newton exactly.

constexpr int    S_DIM      = 8;
constexpr float  KSEL       = 2.0f;
constexpr float  INV_TAU    = 100.0f;
constexpr int    MAX_ITER   = 100;
constexpr int    CAP        = 10;             // fast-path iteration cap (n* ~ 7)
constexpr double TOL        = 1e-3;
constexpr float  FP_SCALE   = 4194304.0f;     // 2^22 fixed point (warp sum < 2^31)
constexpr double FP_SCALE_D = 4194304.0;
constexpr int    NW         = 8;              // warps per 256-thread block
constexpr int    PLANE_ROWS = 4194304;        // rows covered by theta planes

__device__ long long g_sums[CAP];
__device__ long long g_sums_fb[MAX_ITER];
__device__ long long g_tail_fb[MAX_ITER];
__device__ int       g_nstar;
__device__ unsigned  g_done1;
__device__ unsigned  g_done_fb;
__device__ float     g_theta[(size_t)CAP * PLANE_ROWS];   // theta after (i+1) updates

__device__ __forceinline__ float sigmoid_f(float x) {
    return __fdividef(1.0f, 1.0f + __expf(-x));
}

__device__ __forceinline__ void eval_fg(const float t[S_DIM], float theta,
                                        float& f, float& g) {
    float fs = 0.0f, gs = 0.0f;
#pragma unroll
    for (int j = 0; j < S_DIM; ++j) {
        float x = (t[j] - theta) * INV_TAU;
        float m = sigmoid_f(x);
        fs += m;
        gs += m * (1.0f - m);
    }
    f = fs - KSEL;
    g = gs;
}

__device__ __forceinline__ float third_largest(const float t[S_DIM]) {
    float a1 = fmaxf(t[0], t[1]);
    float a2 = fminf(t[0], t[1]);
    float a3 = __int_as_float(0xff800000);  // -inf
#pragma unroll
    for (int j = 2; j < S_DIM; ++j) {
        float v  = t[j];
        float m1 = fmaxf(a1, v);
        float r1 = fminf(a1, v);
        float m2 = fmaxf(a2, r1);
        float r2 = fminf(a2, r1);
        float m3 = fmaxf(a3, r2);
        a1 = m1; a2 = m2; a3 = m3;
    }
    return a3;   // (k+1)-th largest for k=2
}

__device__ __forceinline__ void load_row(const float* __restrict__ s, int row,
                                         float t[S_DIM]) {
    const float4* p = reinterpret_cast<const float4*>(s + (size_t)row * S_DIM);
    float4 v0 = p[0];
    float4 v1 = p[1];
    t[0] = v0.x; t[1] = v0.y; t[2] = v0.z; t[3] = v0.w;
    t[4] = v1.x; t[5] = v1.y; t[6] = v1.z; t[7] = v1.w;
}

__global__ void k_zero() {
    for (int i = threadIdx.x; i < MAX_ITER; i += blockDim.x) {
        g_sums_fb[i] = 0;
        g_tail_fb[i] = 0;
        if (i < CAP) g_sums[i] = 0;
    }
    if (threadIdx.x == 0) {
        g_nstar  = -2;
        g_done1  = 0u;
        g_done_fb = 0u;
    }
}

// ---------------- fast path: pass 1 (exactly CAP iterations) ----------------
__global__ void __launch_bounds__(256) k_pass1(const float* __restrict__ s, int nrows) {
    __shared__ int ss[NW][CAP];
    const int tid  = threadIdx.x;
    const int wid  = tid >> 5;
    const int lane = tid & 31;

    if (tid < NW * CAP) (&ss[0][0])[tid] = 0;
    __syncthreads();

    int row = blockIdx.x * blockDim.x + tid;
    bool valid = row < nrows;
    bool planes = valid && (nrows <= PLANE_ROWS);

    float t[S_DIM];
    float theta = 0.0f;
    if (valid) {
        load_row(s, row, t);
        theta = third_largest(t);
    } else {
#pragma unroll
        for (int j = 0; j < S_DIM; ++j) t[j] = 0.0f;
    }

#pragma unroll 1
    for (int i = 0; i < CAP; ++i) {
        float f, g;
        eval_fg(t, theta, f, g);
        int fx = valid ? __float2int_rn(f * FP_SCALE) : 0;
        int wsum = __reduce_add_sync(0xffffffffu, fx);
        if (lane == 0) ss[wid][i] = wsum;

        if (valid) {
            float thn = theta - __fdividef(f, -100.0f * g);
            if ((g > 0.0f) && (thn != theta)) theta = thn;
            // else: exact fp32 fixed point; update is a no-op, theta unchanged
        }
        if (planes)
            g_theta[(size_t)i * PLANE_ROWS + row] = theta;  // theta after i+1 updates
    }

    __syncthreads();
    for (int idx = tid; idx < CAP; idx += blockDim.x) {
        long long tot = 0;
#pragma unroll
        for (int w = 0; w < NW; ++w) tot += (long long)ss[w][idx];
        if (tot)
            atomicAdd(reinterpret_cast<unsigned long long*>(&g_sums[idx]),
                      (unsigned long long)tot);
    }

    // last block computes n* (fold k_pick into pass1)
    __threadfence();
    __shared__ bool is_last;
    if (tid == 0)
        is_last = (atomicAdd(&g_done1, 1u) == (unsigned)(gridDim.x - 1));
    __syncthreads();
    if (is_last && tid == 0) {
        double denom = (double)nrows * FP_SCALE_D;
        int n = -1;   // -1 => fallback required
        for (int i = 0; i < CAP; ++i) {
            double mean = (double)g_sums[i] / denom;
            if (mean < TOL) { n = i; break; }
        }
        g_nstar = n;
        __threadfence();
    }
}

// ---------------- exact fallback (early-exits when fast path succeeded) ----------------
__global__ void __launch_bounds__(256) k_fb_pass1(const float* __restrict__ s, int nrows) {
    if (g_nstar >= 0) return;   // uniform: fast path found n*

    __shared__ long long ss[NW][MAX_ITER];
    const int tid  = threadIdx.x;
    const int wid  = tid >> 5;
    const int lane = tid & 31;

    for (int i = tid; i < NW * MAX_ITER; i += blockDim.x)
        (&ss[0][0])[i] = 0;
    __syncthreads();

    const int stride = gridDim.x * blockDim.x;
    for (int row = blockIdx.x * blockDim.x + tid; ; row += stride) {
        bool valid = row < nrows;
        if (!__any_sync(0xffffffffu, valid)) break;

        float t[S_DIM];
        float theta = 0.0f;
        if (valid) {
            load_row(s, row, t);
            theta = third_largest(t);
        } else {
#pragma unroll
            for (int j = 0; j < S_DIM; ++j) t[j] = 0.0f;
        }

        bool frozen = !valid;
        int  i = 0;
        int  wsum = 0;

#pragma unroll 1
        for (; i < MAX_ITER; ++i) {
            float f, g;
            eval_fg(t, theta, f, g);
            int fx = valid ? __float2int_rn(f * FP_SCALE) : 0;
            wsum = __reduce_add_sync(0xffffffffu, fx);
            if (lane == 0) ss[wid][i] += (long long)wsum;

            if (!frozen) {
                float thn = theta - __fdividef(f, -100.0f * g);
                if ((g > 0.0f) && (thn != theta)) theta = thn;
                else frozen = true;
            }
            if (__all_sync(0xffffffffu, frozen)) { ++i; break; }
        }

        if (lane == 0 && i < MAX_ITER && wsum != 0)
            atomicAdd(reinterpret_cast<unsigned long long*>(&g_tail_fb[i]),
                      (unsigned long long)(long long)wsum);
    }

    __syncthreads();
    for (int idx = tid; idx < MAX_ITER; idx += blockDim.x) {
        long long tot = 0;
#pragma unroll
        for (int w = 0; w < NW; ++w) tot += ss[w][idx];
        if (tot)
            atomicAdd(reinterpret_cast<unsigned long long*>(&g_sums_fb[idx]),
                      (unsigned long long)tot);
    }

    // last block computes n* (fold k_fb_pick into fallback)
    __threadfence();
    __shared__ bool is_last;
    if (tid == 0)
        is_last = (atomicAdd(&g_done_fb, 1u) == (unsigned)(gridDim.x - 1));
    __syncthreads();
    if (is_last && tid == 0) {
        double denom = (double)nrows * FP_SCALE_D;
        long long carry = 0;
        int n = MAX_ITER;
        for (int i = 0; i < MAX_ITER; ++i) {
            carry += g_tail_fb[i];
            double mean = (double)(g_sums_fb[i] + carry) / denom;
            if (mean < TOL) { n = i; break; }
        }
        g_nstar = n;
        __threadfence();
    }
}

// ---------------- pass 2 ----------------
__global__ void __launch_bounds__(256) k_pass2(const float* __restrict__ s,
                                               float* __restrict__ out, int nrows) {
    int row = blockIdx.x * blockDim.x + threadIdx.x;
    if (row >= nrows) return;

    float t[S_DIM];
    load_row(s, row, t);

    int n = g_nstar;   // uniform across grid
    float theta;
    if (n > 0 && n <= CAP && nrows <= PLANE_ROWS) {
        theta = g_theta[(size_t)(n - 1) * PLANE_ROWS + row];   // theta after n updates
    } else if (n == 0) {
        theta = third_largest(t);
    } else {
        // fallback / oversize: exact Newton replay (n updates; frozen -> no-ops)
        theta = third_largest(t);
#pragma unroll 1
        for (int i = 0; i < n; ++i) {
            float f, g;
            eval_fg(t, theta, f, g);
            float thn = theta - __fdividef(f, -100.0f * g);
            if ((g > 0.0f) && (thn != theta)) theta = thn;
            else break;
        }
    }

    float4 o0, o1;
    o0.x = sigmoid_f((t[0] - theta) * INV_TAU);
    o0.y = sigmoid_f((t[1] - theta) * INV_TAU);
    o0.z = sigmoid_f((t[2] - theta) * INV_TAU);
    o0.w = sigmoid_f((t[3] - theta) * INV_TAU);
    o1.x = sigmoid_f((t[4] - theta) * INV_TAU);
    o1.y = sigmoid_f((t[5] - theta) * INV_TAU);
    o1.z = sigmoid_f((t[6] - theta) * INV_TAU);
    o1.w = sigmoid_f((t[7] - theta) * INV_TAU);

    float4* po = reinterpret_cast<float4*>(out + (size_t)row * S_DIM);
    po[0] = o0;
    po[1] = o1;
}

extern "C" void kernel_launch(void* const* d_in, const int* in_sizes, int n_in,
                              void* d_out, int out_size) {
    const float* s = (const float*)d_in[0];
    float* out = (float*)d_out;
    int nrows = in_sizes[0] / S_DIM;

    k_zero<<<1, 128>>>();

    const int threads = 256;
    int blocks = (nrows + threads - 1) / threads;
    k_pass1<<<blocks, threads>>>(s, nrows);
    k_fb_pass1<<<2960, threads>>>(s, nrows);   // early-exits when fast path succeeded
    k_pass2<<<blocks, threads>>>(s, out, nrows);
}

// round 5
// speedup vs baseline: 7.9162x; 1.0412x over previous
#include <cuda_runtime.h>
#include <math.h>

// SmoothTopKGate: s (nrows, 8) fp32 -> sigmoid((s - theta)/tau).
// n* = first i with mean_rows(f(theta_i)) < TOL (global stop), all rows then
// apply exactly n* Newton updates from theta0 = 3rd largest.
//
// Fast path: pass1 runs CAP1=8 iterations (n* ~ 5-6), exact per-iteration
// f-sums (2^22 fixed point, order-independent -> deterministic), theta
// trajectory stored to global planes; last block picks n*.
// Miss path: k_cont RESUMES from plane[CAP1-1] for iters 8..23 (no restart).
// Deep fallback (n*>=24): exact full-depth recompute; pass2 replays Newton.
// Pass2 reads theta_{n*} from its plane and emits 8 gates (DRAM-bound).

constexpr int    S_DIM      = 8;
constexpr float  KSEL       = 2.0f;
constexpr float  INV_TAU    = 100.0f;
constexpr int    MAX_ITER   = 100;
constexpr int    CAP1       = 8;              // pass1 iterations
constexpr int    CAP2       = 24;             // pass1+cont total planes
constexpr double TOL        = 1e-3;
constexpr float  FP_SCALE   = 4194304.0f;     // 2^22 fixed point (warp sum < 2^31)
constexpr double FP_SCALE_D = 4194304.0;
constexpr int    NW         = 8;              // warps per 256-thread block
constexpr int    PLANE_ROWS = 4194304;        // rows covered by theta planes
constexpr float  CEXP       = 144.26950408889634f;   // 100 * log2(e)

__device__ long long g_sums[CAP2];
__device__ long long g_sums_fb[MAX_ITER];
__device__ long long g_tail_fb[MAX_ITER];
__device__ int       g_nstar;
__device__ unsigned  g_done1, g_done_c, g_done_fb;
__device__ float     g_theta[(size_t)CAP2 * PLANE_ROWS];  // theta after (i+1) updates

// ---------------- helpers ----------------
__device__ __forceinline__ float ex2_approx(float x) {
    float y; asm("ex2.approx.f32 %0, %1;" : "=f"(y) : "f"(x)); return y;
}
__device__ __forceinline__ float rcp_approx(float x) {
    float y; asm("rcp.approx.f32 %0, %1;" : "=f"(y) : "f"(x)); return y;
}

__device__ __forceinline__ float sigmoid_f(float x) {       // exact output path
    return __fdividef(1.0f, 1.0f + __expf(-x));
}

// exact (R4) evaluation — used by deep fallback + pass2 replay
__device__ __forceinline__ void eval_fg(const float t[S_DIM], float theta,
                                        float& f, float& g) {
    float fs = 0.0f, gs = 0.0f;
#pragma unroll
    for (int j = 0; j < S_DIM; ++j) {
        float x = (t[j] - theta) * INV_TAU;
        float m = sigmoid_f(x);
        fs += m;
        gs += m * (1.0f - m);
    }
    f = fs - KSEL;
    g = gs;
}

// fast evaluation: hoisted exp args (b_j = t_j*CEXP) + pairwise reciprocals.
// e clamped to 1e15 so p*q never overflows for mixed pairs -> no inf*0 NaN.
__device__ __forceinline__ void eval_fg_fast(const float b[S_DIM], float theta,
                                             float& f, float& g) {
    float h = theta * CEXP;
    float e[S_DIM];
#pragma unroll
    for (int j = 0; j < S_DIM; ++j)
        e[j] = fminf(ex2_approx(h - b[j]), 1e15f);   // exp(-(t_j-theta)*100)
    float fs = 0.0f, gs = 0.0f;
#pragma unroll
    for (int j = 0; j < S_DIM; j += 2) {
        float p = 1.0f + e[j];
        float q = 1.0f + e[j + 1];
        float r = rcp_approx(p * q);
        float m0 = q * r;
        float m1 = p * r;
        fs += m0; fs += m1;
        gs = fmaf(m0, m0, gs);
        gs = fmaf(m1, m1, gs);
    }
    f = fs - KSEL;
    g = fs - gs;          // sum m(1-m) = sum m - sum m^2
}

__device__ __forceinline__ float third_largest(const float t[S_DIM]) {
    float a1 = fmaxf(t[0], t[1]);
    float a2 = fminf(t[0], t[1]);
    float a3 = __int_as_float(0xff800000);  // -inf
#pragma unroll
    for (int j = 2; j < S_DIM; ++j) {
        float v  = t[j];
        float m1 = fmaxf(a1, v);
        float r1 = fminf(a1, v);
        float m2 = fmaxf(a2, r1);
        float r2 = fminf(a2, r1);
        float m3 = fmaxf(a3, r2);
        a1 = m1; a2 = m2; a3 = m3;
    }
    return a3;   // (k+1)-th largest for k=2
}

__device__ __forceinline__ void load_row(const float* __restrict__ s, int row,
                                         float t[S_DIM]) {
    const float4* p = reinterpret_cast<const float4*>(s + (size_t)row * S_DIM);
    float4 v0 = p[0];
    float4 v1 = p[1];
    t[0] = v0.x; t[1] = v0.y; t[2] = v0.z; t[3] = v0.w;
    t[4] = v1.x; t[5] = v1.y; t[6] = v1.z; t[7] = v1.w;
}

__global__ void k_zero() {
    for (int i = threadIdx.x; i < MAX_ITER; i += blockDim.x) {
        g_sums_fb[i] = 0;
        g_tail_fb[i] = 0;
        if (i < CAP2) g_sums[i] = 0;
    }
    if (threadIdx.x == 0) {
        g_nstar = -2;
        g_done1 = 0u; g_done_c = 0u; g_done_fb = 0u;
    }
}

// ---------------- pass 1: iterations 0..CAP1-1 ----------------
__global__ void __launch_bounds__(256) k_pass1(const float* __restrict__ s, int nrows) {
    __shared__ int ss[NW][CAP1];
    const int tid  = threadIdx.x;
    const int wid  = tid >> 5;
    const int lane = tid & 31;

    if (tid < NW * CAP1) (&ss[0][0])[tid] = 0;
    __syncthreads();

    int row = blockIdx.x * blockDim.x + tid;
    bool valid  = row < nrows;
    bool planes = valid && (nrows <= PLANE_ROWS);

    float t[S_DIM], b[S_DIM];
    float theta = 0.0f;
    if (valid) {
        load_row(s, row, t);
        theta = third_largest(t);
    } else {
#pragma unroll
        for (int j = 0; j < S_DIM; ++j) t[j] = 0.0f;
    }
#pragma unroll
    for (int j = 0; j < S_DIM; ++j) b[j] = t[j] * CEXP;

#pragma unroll 1
    for (int i = 0; i < CAP1; ++i) {
        float f, g;
        eval_fg_fast(b, theta, f, g);
        int fx = valid ? __float2int_rn(f * FP_SCALE) : 0;
        int wsum = __reduce_add_sync(0xffffffffu, fx);
        if (lane == 0) ss[wid][i] = wsum;

        if (valid) {
            float thn = theta - __fdividef(f, -100.0f * g);
            if ((g > 0.0f) && (thn != theta)) theta = thn;
        }
        if (planes)
            g_theta[(size_t)i * PLANE_ROWS + row] = theta;
    }

    __syncthreads();
    for (int idx = tid; idx < CAP1; idx += blockDim.x) {
        long long tot = 0;
#pragma unroll
        for (int w = 0; w < NW; ++w) tot += (long long)ss[w][idx];
        if (tot)
            atomicAdd(reinterpret_cast<unsigned long long*>(&g_sums[idx]),
                      (unsigned long long)tot);
    }

    __threadfence();
    __shared__ bool is_last;
    if (tid == 0)
        is_last = (atomicAdd(&g_done1, 1u) == (unsigned)(gridDim.x - 1));
    __syncthreads();
    if (is_last && tid == 0) {
        double denom = (double)nrows * FP_SCALE_D;
        int n = -1;   // -1 => continuation / fallback required
        for (int i = 0; i < CAP1; ++i) {
            double mean = (double)g_sums[i] / denom;
            if (mean < TOL) { n = i; break; }
        }
        g_nstar = n;
        __threadfence();
    }
}

// ---------------- continuation: iterations CAP1..CAP2-1 (resumes from plane) ----------------
__global__ void __launch_bounds__(256) k_cont(const float* __restrict__ s, int nrows) {
    if (g_nstar != -1) return;            // uniform across grid
    if (nrows > PLANE_ROWS) return;       // planes unavailable -> deep fallback handles

    __shared__ int ss[NW][CAP2 - CAP1];
    const int tid  = threadIdx.x;
    const int wid  = tid >> 5;
    const int lane = tid & 31;

    if (tid < NW * (CAP2 - CAP1)) (&ss[0][0])[tid] = 0;
    __syncthreads();

    int row = blockIdx.x * blockDim.x + tid;
    bool valid = row < nrows;

    float t[S_DIM], b[S_DIM];
    float theta = 0.0f;
    if (valid) {
        load_row(s, row, t);
        theta = g_theta[(size_t)(CAP1 - 1) * PLANE_ROWS + row];  // exact resume
    } else {
#pragma unroll
        for (int j = 0; j < S_DIM; ++j) t[j] = 0.0f;
    }
#pragma unroll
    for (int j = 0; j < S_DIM; ++j) b[j] = t[j] * CEXP;

#pragma unroll 1
    for (int i = CAP1; i < CAP2; ++i) {
        float f, g;
        eval_fg_fast(b, theta, f, g);
        int fx = valid ? __float2int_rn(f * FP_SCALE) : 0;
        int wsum = __reduce_add_sync(0xffffffffu, fx);
        if (lane == 0) ss[wid][i - CAP1] = wsum;

        if (valid) {
            float thn = theta - __fdividef(f, -100.0f * g);
            if ((g > 0.0f) && (thn != theta)) theta = thn;
        }
        if (valid)
            g_theta[(size_t)i * PLANE_ROWS + row] = theta;
    }

    __syncthreads();
    for (int idx = tid; idx < CAP2 - CAP1; idx += blockDim.x) {
        long long tot = 0;
#pragma unroll
        for (int w = 0; w < NW; ++w) tot += (long long)ss[w][idx];
        if (tot)
            atomicAdd(reinterpret_cast<unsigned long long*>(&g_sums[CAP1 + idx]),
                      (unsigned long long)tot);
    }

    __threadfence();
    __shared__ bool is_last;
    if (tid == 0)
        is_last = (atomicAdd(&g_done_c, 1u) == (unsigned)(gridDim.x - 1));
    __syncthreads();
    if (is_last && tid == 0) {
        double denom = (double)nrows * FP_SCALE_D;
        int n = -1;
        for (int i = CAP1; i < CAP2; ++i) {
            double mean = (double)g_sums[i] / denom;
            if (mean < TOL) { n = i; break; }
        }
        g_nstar = n;    // stays -1 if still no crossing -> deep fallback
        __threadfence();
    }
}

// ---------------- deep fallback: exact full depth (early-exits when unused) ----------------
__global__ void __launch_bounds__(256) k_fb_pass1(const float* __restrict__ s, int nrows) {
    if (g_nstar >= 0) return;

    __shared__ long long ss[NW][MAX_ITER];
    const int tid  = threadIdx.x;
    const int wid  = tid >> 5;
    const int lane = tid & 31;

    for (int i = tid; i < NW * MAX_ITER; i += blockDim.x)
        (&ss[0][0])[i] = 0;
    __syncthreads();

    const int stride = gridDim.x * blockDim.x;
    for (int row = blockIdx.x * blockDim.x + tid; ; row += stride) {
        bool valid = row < nrows;
        if (!__any_sync(0xffffffffu, valid)) break;

        float t[S_DIM];
        float theta = 0.0f;
        if (valid) {
            load_row(s, row, t);
            theta = third_largest(t);
        } else {
#pragma unroll
            for (int j = 0; j < S_DIM; ++j) t[j] = 0.0f;
        }

        bool frozen = !valid;
        int  i = 0;
        int  wsum = 0;

#pragma unroll 1
        for (; i < MAX_ITER; ++i) {
            float f, g;
            eval_fg(t, theta, f, g);
            int fx = valid ? __float2int_rn(f * FP_SCALE) : 0;
            wsum = __reduce_add_sync(0xffffffffu, fx);
            if (lane == 0) ss[wid][i] += (long long)wsum;

            if (!frozen) {
                float thn = theta - __fdividef(f, -100.0f * g);
                if ((g > 0.0f) && (thn != theta)) theta = thn;
                else frozen = true;
            }
            if (__all_sync(0xffffffffu, frozen)) { ++i; break; }
        }

        if (lane == 0 && i < MAX_ITER && wsum != 0)
            atomicAdd(reinterpret_cast<unsigned long long*>(&g_tail_fb[i]),
                      (unsigned long long)(long long)wsum);
    }

    __syncthreads();
    for (int idx = tid; idx < MAX_ITER; idx += blockDim.x) {
        long long tot = 0;
#pragma unroll
        for (int w = 0; w < NW; ++w) tot += ss[w][idx];
        if (tot)
            atomicAdd(reinterpret_cast<unsigned long long*>(&g_sums_fb[idx]),
                      (unsigned long long)tot);
    }

    __threadfence();
    __shared__ bool is_last;
    if (tid == 0)
        is_last = (atomicAdd(&g_done_fb, 1u) == (unsigned)(gridDim.x - 1));
    __syncthreads();
    if (is_last && tid == 0) {
        double denom = (double)nrows * FP_SCALE_D;
        long long carry = 0;
        int n = MAX_ITER;
        for (int i = 0; i < MAX_ITER; ++i) {
            carry += g_tail_fb[i];
            double mean = (double)(g_sums_fb[i] + carry) / denom;
            if (mean < TOL) { n = i; break; }
        }
        g_nstar = n;
        __threadfence();
    }
}

// ---------------- pass 2 ----------------
__global__ void __launch_bounds__(256) k_pass2(const float* __restrict__ s,
                                               float* __restrict__ out, int nrows) {
    int row = blockIdx.x * blockDim.x + threadIdx.x;
    if (row >= nrows) return;

    float t[S_DIM];
    load_row(s, row, t);

    int n = g_nstar;   // uniform across grid
    float theta;
    if (n > 0 && n <= CAP2 && nrows <= PLANE_ROWS) {
        theta = g_theta[(size_t)(n - 1) * PLANE_ROWS + row];   // theta after n updates
    } else if (n == 0) {
        theta = third_largest(t);
    } else {
        // deep fallback / oversize: exact Newton replay
        theta = third_largest(t);
#pragma unroll 1
        for (int i = 0; i < n; ++i) {
            float f, g;
            eval_fg(t, theta, f, g);
            float thn = theta - __fdividef(f, -100.0f * g);
            if ((g > 0.0f) && (thn != theta)) theta = thn;
            else break;
        }
    }

    float4 o0, o1;
    o0.x = sigmoid_f((t[0] - theta) * INV_TAU);
    o0.y = sigmoid_f((t[1] - theta) * INV_TAU);
    o0.z = sigmoid_f((t[2] - theta) * INV_TAU);
    o0.w = sigmoid_f((t[3] - theta) * INV_TAU);
    o1.x = sigmoid_f((t[4] - theta) * INV_TAU);
    o1.y = sigmoid_f((t[5] - theta) * INV_TAU);
    o1.z = sigmoid_f((t[6] - theta) * INV_TAU);
    o1.w = sigmoid_f((t[7] - theta) * INV_TAU);

    float4* po = reinterpret_cast<float4*>(out + (size_t)row * S_DIM);
    po[0] = o0;
    po[1] = o1;
}

extern "C" void kernel_launch(void* const* d_in, const int* in_sizes, int n_in,
                              void* d_out, int out_size) {
    const float* s = (const float*)d_in[0];
    float* out = (float*)d_out;
    int nrows = in_sizes[0] / S_DIM;

    k_zero<<<1, 128>>>();

    const int threads = 256;
    int blocks = (nrows + threads - 1) / threads;
    k_pass1<<<blocks, threads>>>(s, nrows);
    k_cont<<<blocks, threads>>>(s, nrows);      // early-exits when pass1 found n*
    k_fb_pass1<<<2960, threads>>>(s, nrows);    // early-exits unless n* >= CAP2
    k_pass2<<<blocks, threads>>>(s, out, nrows);
}

// round 8
// speedup vs baseline: 8.2763x; 1.0455x over previous
#include <cuda_runtime.h>
#include <math.h>

// SmoothTopKGate: s (nrows, 8) fp32 -> sigmoid((s - theta)/tau).
// n* = first i with mean_rows(f(theta_i)) < TOL (global stop), all rows then
// apply exactly n* Newton updates from theta0 = 3rd largest.
//
// pass1: CAP1=7 iterations, 2 rows/thread, tanh-form sigmoid (1 MUFU/elem),
//        exact fixed-point per-iteration f-sums, theta planes, last-block pick.
// cont:  resumes from plane[CAP1-1] for iters 7..23 if no crossing (cold).
// fb:    exact full-depth recompute for n*>=24 (cold).
// pass2: reads theta_{n*} plane, emits 8 gates (DRAM-bound).

constexpr int    S_DIM      = 8;
constexpr float  KSEL       = 2.0f;
constexpr float  INV_TAU    = 100.0f;
constexpr int    MAX_ITER   = 100;
constexpr int    CAP1       = 7;              // pass1 iterations (n* ~ 5)
constexpr int    CAP2       = 24;             // pass1+cont total planes
constexpr double TOL        = 1e-3;
constexpr float  FP_SCALE   = 4194304.0f;     // 2^22 fixed point
constexpr double FP_SCALE_D = 4194304.0;
constexpr int    NW         = 8;              // warps per 256-thread block
constexpr int    PLANE_ROWS = 4194304;
constexpr float  CEXP       = 144.26950408889634f;   // 100 * log2(e)  (cont path)
constexpr float  CHALF      = 50.0f;                 // (1/tau)/2 for tanh arg

__device__ long long g_sums[CAP2];
__device__ long long g_sums_fb[MAX_ITER];
__device__ long long g_tail_fb[MAX_ITER];
__device__ int       g_nstar;
__device__ unsigned  g_done1, g_done_c, g_done_fb;
__device__ float     g_theta[(size_t)CAP2 * PLANE_ROWS];  // theta after (i+1) updates

// ---------------- helpers ----------------
__device__ __forceinline__ float tanh_approx(float x) {
    float y; asm("tanh.approx.f32 %0, %1;" : "=f"(y) : "f"(x)); return y;
}
__device__ __forceinline__ float ex2_approx(float x) {
    float y; asm("ex2.approx.f32 %0, %1;" : "=f"(y) : "f"(x)); return y;
}
__device__ __forceinline__ float rcp_approx(float x) {
    float y; asm("rcp.approx.f32 %0, %1;" : "=f"(y) : "f"(x)); return y;
}

__device__ __forceinline__ float sigmoid_f(float x) {       // exact output path
    return __fdividef(1.0f, 1.0f + __expf(-x));
}

// exact (R4) evaluation — deep fallback + pass2 replay
__device__ __forceinline__ void eval_fg(const float t[S_DIM], float theta,
                                        float& f, float& g) {
    float fs = 0.0f, gs = 0.0f;
#pragma unroll
    for (int j = 0; j < S_DIM; ++j) {
        float x = (t[j] - theta) * INV_TAU;
        float m = sigmoid_f(x);
        fs += m;
        gs += m * (1.0f - m);
    }
    f = fs - KSEL;
    g = gs;
}

// tanh-form evaluation: b_j = t_j*50 hoisted; m = 0.5+0.5*tanh(b_j - theta*50)
// f = sum m - 2 = 2 + 0.5*sum(t);  g = sum m(1-m) = 2 - 0.25*sum(t^2)
__device__ __forceinline__ void eval_fg_tanh(const float b[S_DIM], float theta,
                                             float& f, float& g) {
    float h = theta * CHALF;
    float st = 0.0f, sq = 0.0f;
#pragma unroll
    for (int j = 0; j < S_DIM; ++j) {
        float th = tanh_approx(b[j] - h);
        st += th;
        sq = fmaf(th, th, sq);
    }
    f = fmaf(0.5f, st, 2.0f);
    g = fmaf(-0.25f, sq, 2.0f);
}

// R5 fast evaluation (cont path)
__device__ __forceinline__ void eval_fg_fast(const float b[S_DIM], float theta,
                                             float& f, float& g) {
    float h = theta * CEXP;
    float e[S_DIM];
#pragma unroll
    for (int j = 0; j < S_DIM; ++j)
        e[j] = fminf(ex2_approx(h - b[j]), 1e15f);
    float fs = 0.0f, gs = 0.0f;
#pragma unroll
    for (int j = 0; j < S_DIM; j += 2) {
        float p = 1.0f + e[j];
        float q = 1.0f + e[j + 1];
        float r = rcp_approx(p * q);
        float m0 = q * r;
        float m1 = p * r;
        fs += m0; fs += m1;
        gs = fmaf(m0, m0, gs);
        gs = fmaf(m1, m1, gs);
    }
    f = fs - KSEL;
    g = fs - gs;
}

__device__ __forceinline__ float third_largest(const float t[S_DIM]) {
    float a1 = fmaxf(t[0], t[1]);
    float a2 = fminf(t[0], t[1]);
    float a3 = __int_as_float(0xff800000);  // -inf
#pragma unroll
    for (int j = 2; j < S_DIM; ++j) {
        float v  = t[j];
        float m1 = fmaxf(a1, v);
        float r1 = fminf(a1, v);
        float m2 = fmaxf(a2, r1);
        float r2 = fminf(a2, r1);
        float m3 = fmaxf(a3, r2);
        a1 = m1; a2 = m2; a3 = m3;
    }
    return a3;   // (k+1)-th largest for k=2
}

__device__ __forceinline__ void load_row(const float* __restrict__ s, int row,
                                         float t[S_DIM]) {
    const float4* p = reinterpret_cast<const float4*>(s + (size_t)row * S_DIM);
    float4 v0 = p[0];
    float4 v1 = p[1];
    t[0] = v0.x; t[1] = v0.y; t[2] = v0.z; t[3] = v0.w;
    t[4] = v1.x; t[5] = v1.y; t[6] = v1.z; t[7] = v1.w;
}

__global__ void k_zero() {
    for (int i = threadIdx.x; i < MAX_ITER; i += blockDim.x) {
        g_sums_fb[i] = 0;
        g_tail_fb[i] = 0;
        if (i < CAP2) g_sums[i] = 0;
    }
    if (threadIdx.x == 0) {
        g_nstar = -2;
        g_done1 = 0u; g_done_c = 0u; g_done_fb = 0u;
    }
}

// ---------------- pass 1: iterations 0..CAP1-1, 2 rows/thread ----------------
__global__ void __launch_bounds__(256) k_pass1(const float* __restrict__ s, int nrows) {
    __shared__ int ss[NW][CAP1];
    const int tid  = threadIdx.x;
    const int wid  = tid >> 5;
    const int lane = tid & 31;

    if (tid < NW * CAP1) (&ss[0][0])[tid] = 0;
    __syncthreads();

    const int T    = gridDim.x * blockDim.x;
    const int rowA = blockIdx.x * blockDim.x + tid;
    const int rowB = rowA + T;
    const bool va = rowA < nrows;
    const bool vb = rowB < nrows;
    const bool planes = (nrows <= PLANE_ROWS);

    float bA[S_DIM], bB[S_DIM];
    float thA = 0.0f, thB = 0.0f;
    {
        float t[S_DIM];
        if (va) {
            load_row(s, rowA, t);
            thA = third_largest(t);
#pragma unroll
            for (int j = 0; j < S_DIM; ++j) bA[j] = t[j] * CHALF;
        } else {
#pragma unroll
            for (int j = 0; j < S_DIM; ++j) bA[j] = 0.0f;
        }
        if (vb) {
            load_row(s, rowB, t);
            thB = third_largest(t);
#pragma unroll
            for (int j = 0; j < S_DIM; ++j) bB[j] = t[j] * CHALF;
        } else {
#pragma unroll
            for (int j = 0; j < S_DIM; ++j) bB[j] = 0.0f;
        }
    }

#pragma unroll 1
    for (int i = 0; i < CAP1; ++i) {
        float fA, gA, fB, gB;
        eval_fg_tanh(bA, thA, fA, gA);
        eval_fg_tanh(bB, thB, fB, gB);

        int fx = (va ? __float2int_rn(fA * FP_SCALE) : 0)
               + (vb ? __float2int_rn(fB * FP_SCALE) : 0);
        int wsum = __reduce_add_sync(0xffffffffu, fx);
        if (lane == 0) ss[wid][i] = wsum;

        if (va) {
            float thn = fmaf(fA * 0.01f, rcp_approx(gA), thA);   // theta + f/(100 g)
            if ((gA > 0.0f) && (thn != thA)) thA = thn;
        }
        if (vb) {
            float thn = fmaf(fB * 0.01f, rcp_approx(gB), thB);
            if ((gB > 0.0f) && (thn != thB)) thB = thn;
        }
        if (planes) {
            if (va) g_theta[(size_t)i * PLANE_ROWS + rowA] = thA;
            if (vb) g_theta[(size_t)i * PLANE_ROWS + rowB] = thB;
        }
    }

    __syncthreads();
    for (int idx = tid; idx < CAP1; idx += blockDim.x) {
        long long tot = 0;
#pragma unroll
        for (int w = 0; w < NW; ++w) tot += (long long)ss[w][idx];
        if (tot)
            atomicAdd(reinterpret_cast<unsigned long long*>(&g_sums[idx]),
                      (unsigned long long)tot);
    }

    __threadfence();
    __shared__ bool is_last;
    if (tid == 0)
        is_last = (atomicAdd(&g_done1, 1u) == (unsigned)(gridDim.x - 1));
    __syncthreads();
    if (is_last && tid == 0) {
        double denom = (double)nrows * FP_SCALE_D;
        int n = -1;   // -1 => continuation / fallback required
        for (int i = 0; i < CAP1; ++i) {
            double mean = (double)g_sums[i] / denom;
            if (mean < TOL) { n = i; break; }
        }
        g_nstar = n;
        __threadfence();
    }
}

// ---------------- continuation: iterations CAP1..CAP2-1 (cold) ----------------
__global__ void __launch_bounds__(256) k_cont(const float* __restrict__ s, int nrows) {
    if (g_nstar != -1) return;
    if (nrows > PLANE_ROWS) return;

    __shared__ int ss[NW][CAP2 - CAP1];
    const int tid  = threadIdx.x;
    const int wid  = tid >> 5;
    const int lane = tid & 31;

    if (tid < NW * (CAP2 - CAP1)) (&ss[0][0])[tid] = 0;
    __syncthreads();

    int row = blockIdx.x * blockDim.x + tid;
    bool valid = row < nrows;

    float t[S_DIM], b[S_DIM];
    float theta = 0.0f;
    if (valid) {
        load_row(s, row, t);
        theta = g_theta[(size_t)(CAP1 - 1) * PLANE_ROWS + row];  // exact resume
    } else {
#pragma unroll
        for (int j = 0; j < S_DIM; ++j) t[j] = 0.0f;
    }
#pragma unroll
    for (int j = 0; j < S_DIM; ++j) b[j] = t[j] * CEXP;

#pragma unroll 1
    for (int i = CAP1; i < CAP2; ++i) {
        float f, g;
        eval_fg_fast(b, theta, f, g);
        int fx = valid ? __float2int_rn(f * FP_SCALE) : 0;
        int wsum = __reduce_add_sync(0xffffffffu, fx);
        if (lane == 0) ss[wid][i - CAP1] = wsum;

        if (valid) {
            float thn = theta - __fdividef(f, -100.0f * g);
            if ((g > 0.0f) && (thn != theta)) theta = thn;
        }
        if (valid)
            g_theta[(size_t)i * PLANE_ROWS + row] = theta;
    }

    __syncthreads();
    for (int idx = tid; idx < CAP2 - CAP1; idx += blockDim.x) {
        long long tot = 0;
#pragma unroll
        for (int w = 0; w < NW; ++w) tot += (long long)ss[w][idx];
        if (tot)
            atomicAdd(reinterpret_cast<unsigned long long*>(&g_sums[CAP1 + idx]),
                      (unsigned long long)tot);
    }

    __threadfence();
    __shared__ bool is_last;
    if (tid == 0)
        is_last = (atomicAdd(&g_done_c, 1u) == (unsigned)(gridDim.x - 1));
    __syncthreads();
    if (is_last && tid == 0) {
        double denom = (double)nrows * FP_SCALE_D;
        int n = -1;
        for (int i = CAP1; i < CAP2; ++i) {
            double mean = (double)g_sums[i] / denom;
            if (mean < TOL) { n = i; break; }
        }
        g_nstar = n;    // stays -1 -> deep fallback
        __threadfence();
    }
}

// ---------------- deep fallback: exact full depth (cold) ----------------
__global__ void __launch_bounds__(256) k_fb_pass1(const float* __restrict__ s, int nrows) {
    if (g_nstar >= 0) return;

    __shared__ long long ss[NW][MAX_ITER];
    const int tid  = threadIdx.x;
    const int wid  = tid >> 5;
    const int lane = tid & 31;

    for (int i = tid; i < NW * MAX_ITER; i += blockDim.x)
        (&ss[0][0])[i] = 0;
    __syncthreads();

    const int stride = gridDim.x * blockDim.x;
    for (int row = blockIdx.x * blockDim.x + tid; ; row += stride) {
        bool valid = row < nrows;
        if (!__any_sync(0xffffffffu, valid)) break;

        float t[S_DIM];
        float theta = 0.0f;
        if (valid) {
            load_row(s, row, t);
            theta = third_largest(t);
        } else {
#pragma unroll
            for (int j = 0; j < S_DIM; ++j) t[j] = 0.0f;
        }

        bool frozen = !valid;
        int  i = 0;
        int  wsum = 0;

#pragma unroll 1
        for (; i < MAX_ITER; ++i) {
            float f, g;
            eval_fg(t, theta, f, g);
            int fx = valid ? __float2int_rn(f * FP_SCALE) : 0;
            wsum = __reduce_add_sync(0xffffffffu, fx);
            if (lane == 0) ss[wid][i] += (long long)wsum;

            if (!frozen) {
                float thn = theta - __fdividef(f, -100.0f * g);
                if ((g > 0.0f) && (thn != theta)) theta = thn;
                else frozen = true;
            }
            if (__all_sync(0xffffffffu, frozen)) { ++i; break; }
        }

        if (lane == 0 && i < MAX_ITER && wsum != 0)
            atomicAdd(reinterpret_cast<unsigned long long*>(&g_tail_fb[i]),
                      (unsigned long long)(long long)wsum);
    }

    __syncthreads();
    for (int idx = tid; idx < MAX_ITER; idx += blockDim.x) {
        long long tot = 0;
#pragma unroll
        for (int w = 0; w < NW; ++w) tot += ss[w][idx];
        if (tot)
            atomicAdd(reinterpret_cast<unsigned long long*>(&g_sums_fb[idx]),
                      (unsigned long long)tot);
    }

    __threadfence();
    __shared__ bool is_last;
    if (tid == 0)
        is_last = (atomicAdd(&g_done_fb, 1u) == (unsigned)(gridDim.x - 1));
    __syncthreads();
    if (is_last && tid == 0) {
        double denom = (double)nrows * FP_SCALE_D;
        long long carry = 0;
        int n = MAX_ITER;
        for (int i = 0; i < MAX_ITER; ++i) {
            carry += g_tail_fb[i];
            double mean = (double)(g_sums_fb[i] + carry) / denom;
            if (mean < TOL) { n = i; break; }
        }
        g_nstar = n;
        __threadfence();
    }
}

// ---------------- pass 2 ----------------
__global__ void __launch_bounds__(256) k_pass2(const float* __restrict__ s,
                                               float* __restrict__ out, int nrows) {
    int row = blockIdx.x * blockDim.x + threadIdx.x;
    if (row >= nrows) return;

    float t[S_DIM];
    load_row(s, row, t);

    int n = g_nstar;   // uniform across grid
    float theta;
    if (n > 0 && n <= CAP2 && nrows <= PLANE_ROWS) {
        theta = g_theta[(size_t)(n - 1) * PLANE_ROWS + row];   // theta after n updates
    } else if (n == 0) {
        theta = third_largest(t);
    } else {
        theta = third_largest(t);
#pragma unroll 1
        for (int i = 0; i < n; ++i) {
            float f, g;
            eval_fg(t, theta, f, g);
            float thn = theta - __fdividef(f, -100.0f * g);
            if ((g > 0.0f) && (thn != theta)) theta = thn;
            else break;
        }
    }

    float4 o0, o1;
    o0.x = sigmoid_f((t[0] - theta) * INV_TAU);
    o0.y = sigmoid_f((t[1] - theta) * INV_TAU);
    o0.z = sigmoid_f((t[2] - theta) * INV_TAU);
    o0.w = sigmoid_f((t[3] - theta) * INV_TAU);
    o1.x = sigmoid_f((t[4] - theta) * INV_TAU);
    o1.y = sigmoid_f((t[5] - theta) * INV_TAU);
    o1.z = sigmoid_f((t[6] - theta) * INV_TAU);
    o1.w = sigmoid_f((t[7] - theta) * INV_TAU);

    float4* po = reinterpret_cast<float4*>(out + (size_t)row * S_DIM);
    po[0] = o0;
    po[1] = o1;
}

extern "C" void kernel_launch(void* const* d_in, const int* in_sizes, int n_in,
                              void* d_out, int out_size) {
    const float* s = (const float*)d_in[0];
    float* out = (float*)d_out;
    int nrows = in_sizes[0] / S_DIM;

    k_zero<<<1, 128>>>();

    const int threads = 256;
    int blocks  = (nrows + threads - 1) / threads;
    int blocks2 = (nrows + 2 * threads - 1) / (2 * threads);   // 2 rows/thread
    k_pass1<<<blocks2, threads>>>(s, nrows);
    k_cont<<<blocks, threads>>>(s, nrows);      // cold unless n* >= CAP1
    k_fb_pass1<<<2960, threads>>>(s, nrows);    // cold unless n* >= CAP2
    k_pass2<<<blocks, threads>>>(s, out, nrows);
}